// round 1
// baseline (speedup 1.0000x reference)
#include <cuda_runtime.h>

#define N_NODES 50000
#define N_EDGES 600000
#define D 128

// Scratch (allocation-free rule: device globals)
__device__ float g_h[(size_t)N_NODES * D];     // scaled features / layer activations
__device__ float g_agg[(size_t)N_NODES * D];   // scatter-add accumulator
__device__ float g_dout[N_NODES];              // deg_out^{-1/2}
__device__ float g_din[N_NODES];               // deg_in^{-1/2}

// ---------------------------------------------------------------------------
// Degree computation
// ---------------------------------------------------------------------------
__global__ void deg_zero_kernel() {
    int i = blockIdx.x * blockDim.x + threadIdx.x;
    if (i < N_NODES) { g_dout[i] = 0.0f; g_din[i] = 0.0f; }
}

__global__ void deg_count_kernel(const int* __restrict__ src,
                                 const int* __restrict__ dst) {
    int e = blockIdx.x * blockDim.x + threadIdx.x;
    if (e < N_EDGES) {
        atomicAdd(&g_dout[src[e]], 1.0f);
        atomicAdd(&g_din[dst[e]], 1.0f);
    }
}

__global__ void deg_finalize_kernel() {
    int i = blockIdx.x * blockDim.x + threadIdx.x;
    if (i < N_NODES) {
        g_dout[i] = rsqrtf(fmaxf(g_dout[i], 1.0f));
        g_din[i]  = rsqrtf(fmaxf(g_din[i], 1.0f));
    }
}

// ---------------------------------------------------------------------------
// Layer-1 prologue: g_h = features * dout_isqrt (row-wise), g_agg = 0
// ---------------------------------------------------------------------------
__global__ void scale_and_zero_kernel(const float* __restrict__ feat) {
    int i = blockIdx.x * blockDim.x + threadIdx.x;
    if (i < N_NODES * D) {
        g_h[i] = feat[i] * g_dout[i >> 7];   // D == 128
        g_agg[i] = 0.0f;
    }
}

__global__ void zero_agg_kernel() {
    int i = blockIdx.x * blockDim.x + threadIdx.x;
    if (i < N_NODES * D) g_agg[i] = 0.0f;
}

// ---------------------------------------------------------------------------
// Edge scatter: warp per edge. Lane l gathers h[src][4l..4l+3] (float4) and
// atomically adds into agg[dst][4l..4l+3].
// ---------------------------------------------------------------------------
__global__ void scatter_kernel(const int* __restrict__ src,
                               const int* __restrict__ dst) {
    int gtid = blockIdx.x * blockDim.x + threadIdx.x;
    int e    = gtid >> 5;
    int lane = gtid & 31;
    if (e >= N_EDGES) return;
    int s = src[e];
    int d = dst[e];
    const float4* hp = reinterpret_cast<const float4*>(g_h + (size_t)s * D);
    float4 v = hp[lane];
    float* ap = g_agg + (size_t)d * D + lane * 4;
    atomicAdd(ap + 0, v.x);
    atomicAdd(ap + 1, v.y);
    atomicAdd(ap + 2, v.z);
    atomicAdd(ap + 3, v.w);
}

// ---------------------------------------------------------------------------
// GEMM epilogue: out[n, :] = f( din[n] * (agg[n,:] @ W) + b ) [* dout[n]]
// K fixed at 128, KC=32 chunks. blockDim = (M, ROWS).
// ---------------------------------------------------------------------------
template <int M, int ROWS, bool RELU, bool SCALE_OUT>
__global__ void gemm_kernel(const float* __restrict__ A,   // [N, 128]
                            const float* __restrict__ W,   // [128, M]
                            const float* __restrict__ bias,// [M]
                            float* __restrict__ out)       // [N, M]
{
    constexpr int KC = 32;
    __shared__ float Ws[KC][M + 1];
    __shared__ float As[ROWS][KC + 1];

    int tx = threadIdx.x;            // 0..M-1 (output column)
    int ty = threadIdx.y;            // 0..ROWS-1
    int row = blockIdx.x * ROWS + ty;
    int tid = ty * M + tx;
    constexpr int NT = M * ROWS;

    float acc = 0.0f;

    for (int kc = 0; kc < D; kc += KC) {
        // Load W chunk [KC, M]
        for (int idx = tid; idx < KC * M; idx += NT) {
            int k = idx / M, j = idx % M;
            Ws[k][j] = W[(size_t)(kc + k) * M + j];
        }
        // Load A chunk [ROWS, KC]
        for (int idx = tid; idx < ROWS * KC; idx += NT) {
            int r = idx / KC, k = idx % KC;
            int rr = blockIdx.x * ROWS + r;
            As[r][k] = (rr < N_NODES) ? A[(size_t)rr * D + kc + k] : 0.0f;
        }
        __syncthreads();
        #pragma unroll
        for (int k = 0; k < KC; k++)
            acc += As[ty][k] * Ws[k][tx];
        __syncthreads();
    }

    if (row < N_NODES) {
        float val = acc * g_din[row] + bias[tx];
        if (RELU) val = fmaxf(val, 0.0f);
        if (SCALE_OUT) val *= g_dout[row];   // pre-scale for next layer's gather
        out[(size_t)row * M + tx] = val;
    }
}

// ---------------------------------------------------------------------------
// Launch
// ---------------------------------------------------------------------------
extern "C" void kernel_launch(void* const* d_in, const int* in_sizes, int n_in,
                              void* d_out, int out_size) {
    const float* features = (const float*)d_in[0];
    const int*   src      = (const int*)d_in[1];
    const int*   dst      = (const int*)d_in[2];
    const float* W1       = (const float*)d_in[3];
    const float* b1       = (const float*)d_in[4];
    const float* W2       = (const float*)d_in[5];
    const float* b2       = (const float*)d_in[6];
    const float* W3       = (const float*)d_in[7];
    const float* b3       = (const float*)d_in[8];
    float* out = (float*)d_out;

    float* h_ptr;
    float* agg_ptr;
    cudaGetSymbolAddress((void**)&h_ptr, g_h);
    cudaGetSymbolAddress((void**)&agg_ptr, g_agg);

    const int T = 256;
    int nodeBlocks  = (N_NODES + T - 1) / T;
    int edgeBlocks  = (N_EDGES + T - 1) / T;
    int elemBlocks  = (N_NODES * D + T - 1) / T;
    int warpBlocks  = (N_EDGES * 32 + T - 1) / T;

    // Degrees
    deg_zero_kernel<<<nodeBlocks, T>>>();
    deg_count_kernel<<<edgeBlocks, T>>>(src, dst);
    deg_finalize_kernel<<<nodeBlocks, T>>>();

    // ---- Layer 1 ----
    scale_and_zero_kernel<<<elemBlocks, T>>>(features);
    scatter_kernel<<<warpBlocks, T>>>(src, dst);
    {
        dim3 bd(128, 4);
        int grid = (N_NODES + 4 - 1) / 4;
        gemm_kernel<128, 4, true, true><<<grid, bd>>>(agg_ptr, W1, b1, h_ptr);
    }

    // ---- Layer 2 ----
    zero_agg_kernel<<<elemBlocks, T>>>();
    scatter_kernel<<<warpBlocks, T>>>(src, dst);
    {
        dim3 bd(128, 4);
        int grid = (N_NODES + 4 - 1) / 4;
        gemm_kernel<128, 4, true, true><<<grid, bd>>>(agg_ptr, W2, b2, h_ptr);
    }

    // ---- Layer 3 ----
    zero_agg_kernel<<<elemBlocks, T>>>();
    scatter_kernel<<<warpBlocks, T>>>(src, dst);
    {
        dim3 bd(16, 16);
        int grid = (N_NODES + 16 - 1) / 16;
        gemm_kernel<16, 16, false, false><<<grid, bd>>>(agg_ptr, W3, b3, out);
    }
}

// round 2
// speedup vs baseline: 3.7639x; 3.7639x over previous
#include <cuda_runtime.h>

#define N_NODES 50000
#define N_EDGES 600000
#define D 128

// ---------------------------------------------------------------------------
// Scratch (allocation-free rule: device globals)
// ---------------------------------------------------------------------------
__device__ float g_h[(size_t)N_NODES * D];     // activations (pre-scaled by dout^-1/2)
__device__ float g_agg[(size_t)N_NODES * D];   // aggregated neighborhood
__device__ float g_dout[N_NODES];              // deg_out^{-1/2}
__device__ float g_din[N_NODES];               // deg_in^{-1/2}
__device__ int   g_cnt_out[N_NODES];
__device__ int   g_cnt_in[N_NODES];
__device__ int   g_cursor[N_NODES];
__device__ int   g_offs[N_NODES + 1];
__device__ int   g_csr_src[N_EDGES];

// ---------------------------------------------------------------------------
// Degree histograms (int atomics, cheap) + cursor zero
// ---------------------------------------------------------------------------
__global__ void deg_zero_kernel() {
    int i = blockIdx.x * blockDim.x + threadIdx.x;
    if (i < N_NODES) { g_cnt_out[i] = 0; g_cnt_in[i] = 0; g_cursor[i] = 0; }
}

__global__ void deg_count_kernel(const int* __restrict__ src,
                                 const int* __restrict__ dst) {
    int e = blockIdx.x * blockDim.x + threadIdx.x;
    if (e < N_EDGES) {
        atomicAdd(&g_cnt_out[src[e]], 1);
        atomicAdd(&g_cnt_in[dst[e]], 1);
    }
}

__global__ void deg_finalize_kernel() {
    int i = blockIdx.x * blockDim.x + threadIdx.x;
    if (i < N_NODES) {
        g_dout[i] = rsqrtf((float)max(g_cnt_out[i], 1));
        g_din[i]  = rsqrtf((float)max(g_cnt_in[i], 1));
    }
}

// ---------------------------------------------------------------------------
// Exclusive scan of in-degree histogram -> g_offs. Single block, 1024 threads.
// ---------------------------------------------------------------------------
__global__ void scan_kernel() {
    __shared__ int sums[1024];
    const int CH = (N_NODES + 1023) / 1024;   // 49
    int t = threadIdx.x;
    int base = t * CH;
    int s = 0;
    for (int i = 0; i < CH; i++) {
        int idx = base + i;
        if (idx < N_NODES) s += g_cnt_in[idx];
    }
    sums[t] = s;
    __syncthreads();
    // Hillis-Steele inclusive scan
    for (int off = 1; off < 1024; off <<= 1) {
        int v = (t >= off) ? sums[t - off] : 0;
        __syncthreads();
        sums[t] += v;
        __syncthreads();
    }
    int excl = (t == 0) ? 0 : sums[t - 1];
    for (int i = 0; i < CH; i++) {
        int idx = base + i;
        if (idx < N_NODES) {
            g_offs[idx] = excl;
            excl += g_cnt_in[idx];
        }
    }
    if (t == 1023) g_offs[N_NODES] = excl;   // == N_EDGES
}

// ---------------------------------------------------------------------------
// Fill CSR: bucket edges by dst (order within bucket arbitrary — sum commutes
// up to fp rounding, well inside 1e-3)
// ---------------------------------------------------------------------------
__global__ void fill_kernel(const int* __restrict__ src,
                            const int* __restrict__ dst) {
    int e = blockIdx.x * blockDim.x + threadIdx.x;
    if (e < N_EDGES) {
        int d = dst[e];
        int pos = g_offs[d] + atomicAdd(&g_cursor[d], 1);
        g_csr_src[pos] = src[e];
    }
}

// ---------------------------------------------------------------------------
// Layer-1 prologue: g_h = features * dout^{-1/2} (row-wise)
// ---------------------------------------------------------------------------
__global__ void scale_kernel(const float* __restrict__ feat) {
    int i = blockIdx.x * blockDim.x + threadIdx.x;
    if (i < N_NODES * D) g_h[i] = feat[i] * g_dout[i >> 7];   // D == 128
}

// ---------------------------------------------------------------------------
// Gather aggregation: warp per dst node. Lane l owns floats [4l,4l+4).
// Unroll 4 with independent accumulators for MLP.
// ---------------------------------------------------------------------------
__global__ void agg_kernel() {
    int gtid = blockIdx.x * blockDim.x + threadIdx.x;
    int node = gtid >> 5;
    int lane = gtid & 31;
    if (node >= N_NODES) return;
    int beg = g_offs[node];
    int end = g_offs[node + 1];

    float4 a0 = {0.f, 0.f, 0.f, 0.f};
    float4 a1 = a0, a2 = a0, a3 = a0;

    int i = beg;
    for (; i + 4 <= end; i += 4) {
        int s0 = g_csr_src[i + 0];
        int s1 = g_csr_src[i + 1];
        int s2 = g_csr_src[i + 2];
        int s3 = g_csr_src[i + 3];
        float4 v0 = ((const float4*)(g_h + (size_t)s0 * D))[lane];
        float4 v1 = ((const float4*)(g_h + (size_t)s1 * D))[lane];
        float4 v2 = ((const float4*)(g_h + (size_t)s2 * D))[lane];
        float4 v3 = ((const float4*)(g_h + (size_t)s3 * D))[lane];
        a0.x += v0.x; a0.y += v0.y; a0.z += v0.z; a0.w += v0.w;
        a1.x += v1.x; a1.y += v1.y; a1.z += v1.z; a1.w += v1.w;
        a2.x += v2.x; a2.y += v2.y; a2.z += v2.z; a2.w += v2.w;
        a3.x += v3.x; a3.y += v3.y; a3.z += v3.z; a3.w += v3.w;
    }
    for (; i < end; i++) {
        int s = g_csr_src[i];
        float4 v = ((const float4*)(g_h + (size_t)s * D))[lane];
        a0.x += v.x; a0.y += v.y; a0.z += v.z; a0.w += v.w;
    }
    float4 r;
    r.x = (a0.x + a1.x) + (a2.x + a3.x);
    r.y = (a0.y + a1.y) + (a2.y + a3.y);
    r.z = (a0.z + a1.z) + (a2.z + a3.z);
    r.w = (a0.w + a1.w) + (a2.w + a3.w);
    ((float4*)(g_agg + (size_t)node * D))[lane] = r;
}

// ---------------------------------------------------------------------------
// Register-tiled GEMM: C[N,128] = A[N,128] @ W[128,128], tile 64 rows x 128
// cols per block (256 threads), 4x8 outputs per thread (cols tx + 16j to
// avoid smem bank conflicts). Epilogue: *din, +bias, relu, *dout.
// ---------------------------------------------------------------------------
template <bool RELU, bool SCALE_OUT>
__global__ __launch_bounds__(256)
void gemm128_kernel(const float* __restrict__ A,
                    const float* __restrict__ W,
                    const float* __restrict__ bias,
                    float* __restrict__ out)
{
    __shared__ float As[32][68];     // k-major [k][row], 272B stride (16B aligned)
    __shared__ float Ws[32][128];

    const int tid = threadIdx.x;
    const int tx = tid & 15;         // col group: cols tx + 16j
    const int ty = tid >> 4;         // row group: rows ty*4 .. ty*4+3
    const int row0 = blockIdx.x * 64;

    float acc[4][8];
    #pragma unroll
    for (int r = 0; r < 4; r++)
        #pragma unroll
        for (int c = 0; c < 8; c++) acc[r][c] = 0.0f;

    for (int kc = 0; kc < D; kc += 32) {
        // A chunk: 64 rows x 32 k, stored transposed (k-major)
        #pragma unroll
        for (int j = 0; j < 2; j++) {
            int f = j * 256 + tid;           // 0..511
            int r = f >> 3;
            int kk = (f & 7) << 2;
            int grow = row0 + r;
            float4 v = make_float4(0.f, 0.f, 0.f, 0.f);
            if (grow < N_NODES)
                v = ((const float4*)(A + (size_t)grow * D + kc))[f & 7];
            As[kk + 0][r] = v.x;
            As[kk + 1][r] = v.y;
            As[kk + 2][r] = v.z;
            As[kk + 3][r] = v.w;
        }
        // W chunk: 32 k x 128 cols, row-major
        #pragma unroll
        for (int j = 0; j < 4; j++) {
            int f = j * 256 + tid;           // 0..1023
            int k = f >> 5;
            int c = (f & 31) << 2;
            float4 v = ((const float4*)(W + (size_t)(kc + k) * D))[f & 31];
            *(float4*)&Ws[k][c] = v;
        }
        __syncthreads();

        #pragma unroll
        for (int k = 0; k < 32; k++) {
            float4 a = *(const float4*)&As[k][ty * 4];
            float wv[8];
            #pragma unroll
            for (int j = 0; j < 8; j++) wv[j] = Ws[k][tx + 16 * j];
            #pragma unroll
            for (int j = 0; j < 8; j++) {
                acc[0][j] += a.x * wv[j];
                acc[1][j] += a.y * wv[j];
                acc[2][j] += a.z * wv[j];
                acc[3][j] += a.w * wv[j];
            }
        }
        __syncthreads();
    }

    #pragma unroll
    for (int r = 0; r < 4; r++) {
        int grow = row0 + ty * 4 + r;
        if (grow < N_NODES) {
            float ds = g_din[grow];
            float os = SCALE_OUT ? g_dout[grow] : 1.0f;
            #pragma unroll
            for (int j = 0; j < 8; j++) {
                int c = tx + 16 * j;
                float v = acc[r][j] * ds + bias[c];
                if (RELU) v = fmaxf(v, 0.0f);
                out[(size_t)grow * D + c] = v * os;
            }
        }
    }
}

// ---------------------------------------------------------------------------
// Small GEMM for the 16-wide output layer (smem-tiled, LDS-bound but tiny)
// ---------------------------------------------------------------------------
template <int M, int ROWS, bool RELU, bool SCALE_OUT>
__global__ void gemm_small_kernel(const float* __restrict__ A,
                                  const float* __restrict__ W,
                                  const float* __restrict__ bias,
                                  float* __restrict__ out)
{
    constexpr int KC = 32;
    __shared__ float Ws[KC][M + 1];
    __shared__ float As[ROWS][KC + 1];

    int tx = threadIdx.x;
    int ty = threadIdx.y;
    int row = blockIdx.x * ROWS + ty;
    int tid = ty * M + tx;
    constexpr int NT = M * ROWS;

    float acc = 0.0f;

    for (int kc = 0; kc < D; kc += KC) {
        for (int idx = tid; idx < KC * M; idx += NT) {
            int k = idx / M, j = idx % M;
            Ws[k][j] = W[(size_t)(kc + k) * M + j];
        }
        for (int idx = tid; idx < ROWS * KC; idx += NT) {
            int r = idx / KC, k = idx % KC;
            int rr = blockIdx.x * ROWS + r;
            As[r][k] = (rr < N_NODES) ? A[(size_t)rr * D + kc + k] : 0.0f;
        }
        __syncthreads();
        #pragma unroll
        for (int k = 0; k < KC; k++)
            acc += As[ty][k] * Ws[k][tx];
        __syncthreads();
    }

    if (row < N_NODES) {
        float val = acc * g_din[row] + bias[tx];
        if (RELU) val = fmaxf(val, 0.0f);
        if (SCALE_OUT) val *= g_dout[row];
        out[(size_t)row * M + tx] = val;
    }
}

// ---------------------------------------------------------------------------
// Launch
// ---------------------------------------------------------------------------
extern "C" void kernel_launch(void* const* d_in, const int* in_sizes, int n_in,
                              void* d_out, int out_size) {
    const float* features = (const float*)d_in[0];
    const int*   src      = (const int*)d_in[1];
    const int*   dst      = (const int*)d_in[2];
    const float* W1       = (const float*)d_in[3];
    const float* b1       = (const float*)d_in[4];
    const float* W2       = (const float*)d_in[5];
    const float* b2       = (const float*)d_in[6];
    const float* W3       = (const float*)d_in[7];
    const float* b3       = (const float*)d_in[8];
    float* out = (float*)d_out;

    float* h_ptr;
    float* agg_ptr;
    cudaGetSymbolAddress((void**)&h_ptr, g_h);
    cudaGetSymbolAddress((void**)&agg_ptr, g_agg);

    const int T = 256;
    int nodeBlocks = (N_NODES + T - 1) / T;
    int edgeBlocks = (N_EDGES + T - 1) / T;
    int elemBlocks = (N_NODES * D + T - 1) / T;
    int aggBlocks  = (N_NODES * 32 + T - 1) / T;   // warp per node
    int gemmBlocks = (N_NODES + 63) / 64;

    // CSR build + degrees
    deg_zero_kernel<<<nodeBlocks, T>>>();
    deg_count_kernel<<<edgeBlocks, T>>>(src, dst);
    scan_kernel<<<1, 1024>>>();
    fill_kernel<<<edgeBlocks, T>>>(src, dst);
    deg_finalize_kernel<<<nodeBlocks, T>>>();

    // ---- Layer 1 ----
    scale_kernel<<<elemBlocks, T>>>(features);
    agg_kernel<<<aggBlocks, T>>>();
    gemm128_kernel<true, true><<<gemmBlocks, 256>>>(agg_ptr, W1, b1, h_ptr);

    // ---- Layer 2 ----
    agg_kernel<<<aggBlocks, T>>>();
    gemm128_kernel<true, true><<<gemmBlocks, 256>>>(agg_ptr, W2, b2, h_ptr);

    // ---- Layer 3 ----
    agg_kernel<<<aggBlocks, T>>>();
    {
        dim3 bd(16, 16);
        int grid = (N_NODES + 15) / 16;
        gemm_small_kernel<16, 16, false, false><<<grid, bd>>>(agg_ptr, W3, b3, out);
    }
}